// round 2
// baseline (speedup 1.0000x reference)
#include <cuda_runtime.h>

#define SEQ    2048
#define DM     1024
#define NH     16
#define HD     64
#define BATCH  4
#define BHN    (BATCH * NH)      // 64
#define TOK    (BATCH * SEQ)     // 8192

// Scratch: [B,H,S,hd] layouts, fp32
__device__ float g_Q [(size_t)BHN * SEQ * HD];
__device__ float g_K [(size_t)BHN * SEQ * HD];
__device__ float g_V [(size_t)BHN * SEQ * HD];
__device__ float g_AO[(size_t)BHN * SEQ * HD];

// ---------------------------------------------------------------------------
// C[m,n] = sum_k A[m,k] * W[n,k] + bias[n]
// AMODE 0: A row-major [M,K].  AMODE 1: A gathered from [B,H,S,hd] layout.
// OMODE 0: C row-major [M,N].  OMODE 1: C scattered to [B,H,S,hd] layout.
// Tiles: 128x128x8, 256 threads, 8x8 micro-tile.
// ---------------------------------------------------------------------------
template<int AMODE, int OMODE>
__global__ __launch_bounds__(256)
void sgemm_kernel(const float* __restrict__ A, const float* __restrict__ W,
                  const float* __restrict__ bias, float* __restrict__ C,
                  int M, int N, int K)
{
    __shared__ float As[8][128];
    __shared__ float Bs[8][128];

    const int tid = threadIdx.x;
    const int tx  = tid & 15;      // 0..15 -> col micro
    const int ty  = tid >> 4;      // 0..15 -> row micro
    const int rowBase = blockIdx.y * 128;
    const int colBase = blockIdx.x * 128;
    const int lr = tid >> 1;             // 0..127
    const int lk = (tid & 1) * 4;        // 0 or 4

    float acc[8][8];
#pragma unroll
    for (int i = 0; i < 8; i++)
#pragma unroll
        for (int j = 0; j < 8; j++) acc[i][j] = 0.f;

    for (int k0 = 0; k0 < K; k0 += 8) {
        const int kk = k0 + lk;
        float4 av, bv;
        {
            const int m = rowBase + lr;
            const float* ap;
            if (AMODE == 0) {
                ap = A + (size_t)m * K + kk;
            } else {
                const int b = m >> 11, s = m & 2047;
                const int h = kk >> 6, d = kk & 63;
                ap = A + (((size_t)(b * NH + h) * SEQ + s) << 6) + d;
            }
            av = *(const float4*)ap;
        }
        bv = *(const float4*)(W + (size_t)(colBase + lr) * K + kk);

        __syncthreads();   // previous compute done before overwrite
        As[lk + 0][lr] = av.x;  As[lk + 1][lr] = av.y;
        As[lk + 2][lr] = av.z;  As[lk + 3][lr] = av.w;
        Bs[lk + 0][lr] = bv.x;  Bs[lk + 1][lr] = bv.y;
        Bs[lk + 2][lr] = bv.z;  Bs[lk + 3][lr] = bv.w;
        __syncthreads();

#pragma unroll
        for (int k2 = 0; k2 < 8; k2++) {
            float a0[8], b0[8];
            float4 t;
            t = *(const float4*)&As[k2][ty * 8];     a0[0]=t.x; a0[1]=t.y; a0[2]=t.z; a0[3]=t.w;
            t = *(const float4*)&As[k2][ty * 8 + 4]; a0[4]=t.x; a0[5]=t.y; a0[6]=t.z; a0[7]=t.w;
            t = *(const float4*)&Bs[k2][tx * 8];     b0[0]=t.x; b0[1]=t.y; b0[2]=t.z; b0[3]=t.w;
            t = *(const float4*)&Bs[k2][tx * 8 + 4]; b0[4]=t.x; b0[5]=t.y; b0[6]=t.z; b0[7]=t.w;
#pragma unroll
            for (int i = 0; i < 8; i++)
#pragma unroll
                for (int j = 0; j < 8; j++)
                    acc[i][j] = fmaf(a0[i], b0[j], acc[i][j]);
        }
    }

#pragma unroll
    for (int i = 0; i < 8; i++) {
        const int m = rowBase + ty * 8 + i;
        const int b = m >> 11, s = m & 2047;
#pragma unroll
        for (int j = 0; j < 8; j += 4) {
            const int n = colBase + tx * 8 + j;
            float4 r;
            r.x = acc[i][j + 0] + bias[n + 0];
            r.y = acc[i][j + 1] + bias[n + 1];
            r.z = acc[i][j + 2] + bias[n + 2];
            r.w = acc[i][j + 3] + bias[n + 3];
            if (OMODE == 0) {
                *(float4*)(C + (size_t)m * N + n) = r;
            } else {
                const int h = n >> 6, d = n & 63;
                *(float4*)(C + (((size_t)(b * NH + h) * SEQ + s) << 6) + d) = r;
            }
        }
    }
}

// ---------------------------------------------------------------------------
// Flash attention, fp32. One CTA handles 64 query rows of one (b,h).
// Q,K stored d-major in smem with xor-swizzle (conflict-limited transpose
// stores, aligned float4 reads). P tile reuses the K buffer.
// 16x16 thread grid, 4x4 micro-tiles. Static smem = exactly 48 KB.
// ---------------------------------------------------------------------------
__global__ __launch_bounds__(256)
void attn_kernel(const float* __restrict__ Qg, const float* __restrict__ Kg,
                 const float* __restrict__ Vg, float* __restrict__ Og)
{
    __shared__ float Qs [64 * 64];   // [d][r^sw]
    __shared__ float KPs[64 * 64];   // K: [d][c^sw], then P: [r][c]
    __shared__ float Vs [64 * 64];   // [k][d]

    const int tid = threadIdx.x;
    const int tx  = tid & 15;
    const int ty  = tid >> 4;
    const int bh  = blockIdx.y;
    const int q0  = blockIdx.x * 64;

    const float* Qb = Qg + ((size_t)bh * SEQ + q0) * HD;
    const float* Kb = Kg + (size_t)bh * SEQ * HD;
    const float* Vb = Vg + (size_t)bh * SEQ * HD;

    // load Q tile, transposed+swizzled: (r,d) -> Qs[d*64 + (r ^ ((d&15)<<2))]
    for (int i = tid; i < 64 * 64; i += 256) {
        const int r = i >> 6, d = i & 63;
        Qs[d * 64 + (r ^ ((d & 15) << 2))] = Qb[i];
    }

    float mi[4], li[4], o[4][4];
#pragma unroll
    for (int i = 0; i < 4; i++) {
        mi[i] = -1e30f; li[i] = 0.f;
#pragma unroll
        for (int j = 0; j < 4; j++) o[i][j] = 0.f;
    }

    for (int kt = 0; kt < SEQ; kt += 64) {
        __syncthreads();   // prior PV finished with KPs / Vs
        for (int i = tid; i < 64 * 64; i += 256) {
            const int r = i >> 6, d = i & 63;
            KPs[d * 64 + (r ^ ((d & 15) << 2))] = Kb[(size_t)kt * HD + i];
            Vs[i] = Vb[(size_t)kt * HD + i];
        }
        __syncthreads();

        // S[r][c] = sum_d Q[r][d] * K[c][d]
        float s[4][4];
#pragma unroll
        for (int i = 0; i < 4; i++)
#pragma unroll
            for (int j = 0; j < 4; j++) s[i][j] = 0.f;

#pragma unroll 16
        for (int d = 0; d < 64; d++) {
            const int sw = (d & 15) << 2;
            float4 qa = *(const float4*)&Qs [d * 64 + ((4 * ty) ^ sw)];
            float4 kb = *(const float4*)&KPs[d * 64 + ((4 * tx) ^ sw)];
            float qr[4] = {qa.x, qa.y, qa.z, qa.w};
            float kr[4] = {kb.x, kb.y, kb.z, kb.w};
#pragma unroll
            for (int i = 0; i < 4; i++)
#pragma unroll
                for (int j = 0; j < 4; j++)
                    s[i][j] = fmaf(qr[i], kr[j], s[i][j]);
        }

        // online softmax (scale 1/sqrt(64) = 0.125)
        float alpha[4];
#pragma unroll
        for (int i = 0; i < 4; i++) {
#pragma unroll
            for (int j = 0; j < 4; j++) s[i][j] *= 0.125f;
            float r = fmaxf(fmaxf(s[i][0], s[i][1]), fmaxf(s[i][2], s[i][3]));
            r = fmaxf(r, __shfl_xor_sync(0xffffffffu, r, 1));
            r = fmaxf(r, __shfl_xor_sync(0xffffffffu, r, 2));
            r = fmaxf(r, __shfl_xor_sync(0xffffffffu, r, 4));
            r = fmaxf(r, __shfl_xor_sync(0xffffffffu, r, 8));
            const float mnew = fmaxf(mi[i], r);
            alpha[i] = __expf(mi[i] - mnew);
            float rs = 0.f;
#pragma unroll
            for (int j = 0; j < 4; j++) {
                s[i][j] = __expf(s[i][j] - mnew);
                rs += s[i][j];
            }
            rs += __shfl_xor_sync(0xffffffffu, rs, 1);
            rs += __shfl_xor_sync(0xffffffffu, rs, 2);
            rs += __shfl_xor_sync(0xffffffffu, rs, 4);
            rs += __shfl_xor_sync(0xffffffffu, rs, 8);
            li[i] = li[i] * alpha[i] + rs;
            mi[i] = mnew;
#pragma unroll
            for (int j = 0; j < 4; j++) o[i][j] *= alpha[i];
        }

        __syncthreads();   // everyone done reading K before overwrite with P
#pragma unroll
        for (int i = 0; i < 4; i++) {
            float4 p = make_float4(s[i][0], s[i][1], s[i][2], s[i][3]);
            *(float4*)&KPs[(4 * ty + i) * 64 + 4 * tx] = p;
        }
        __syncthreads();

        // O[r][d] += sum_k P[r][k] * V[k][d]
#pragma unroll 4
        for (int k4 = 0; k4 < 64; k4 += 4) {
            float4 p4[4];
#pragma unroll
            for (int i = 0; i < 4; i++)
                p4[i] = *(const float4*)&KPs[(4 * ty + i) * 64 + k4];
#pragma unroll
            for (int kk = 0; kk < 4; kk++) {
                float4 vv = *(const float4*)&Vs[(k4 + kk) * 64 + 4 * tx];
                float vr[4] = {vv.x, vv.y, vv.z, vv.w};
                float pr[4] = {kk == 0 ? p4[0].x : kk == 1 ? p4[0].y : kk == 2 ? p4[0].z : p4[0].w,
                               kk == 0 ? p4[1].x : kk == 1 ? p4[1].y : kk == 2 ? p4[1].z : p4[1].w,
                               kk == 0 ? p4[2].x : kk == 1 ? p4[2].y : kk == 2 ? p4[2].z : p4[2].w,
                               kk == 0 ? p4[3].x : kk == 1 ? p4[3].y : kk == 2 ? p4[3].z : p4[3].w};
#pragma unroll
                for (int i = 0; i < 4; i++)
#pragma unroll
                    for (int j = 0; j < 4; j++)
                        o[i][j] = fmaf(pr[i], vr[j], o[i][j]);
            }
        }
    }

    float* Ob = Og + ((size_t)bh * SEQ + q0) * HD;
#pragma unroll
    for (int i = 0; i < 4; i++) {
        const float inv = 1.0f / li[i];
        float4 r = make_float4(o[i][0] * inv, o[i][1] * inv, o[i][2] * inv, o[i][3] * inv);
        *(float4*)&Ob[(4 * ty + i) * 64 + 4 * tx] = r;
    }
}

// ---------------------------------------------------------------------------
extern "C" void kernel_launch(void* const* d_in, const int* in_sizes, int n_in,
                              void* d_out, int out_size)
{
    const float* q  = (const float*)d_in[0];
    const float* k  = (const float*)d_in[1];
    const float* v  = (const float*)d_in[2];
    const float* Wq = (const float*)d_in[3];
    const float* bq = (const float*)d_in[4];
    const float* Wk = (const float*)d_in[5];
    const float* bk = (const float*)d_in[6];
    const float* Wv = (const float*)d_in[7];
    const float* bv = (const float*)d_in[8];
    const float* Wo = (const float*)d_in[9];
    const float* bo = (const float*)d_in[10];
    float* out = (float*)d_out;

    float *Qb, *Kb, *Vb, *Ob;
    cudaGetSymbolAddress((void**)&Qb, g_Q);
    cudaGetSymbolAddress((void**)&Kb, g_K);
    cudaGetSymbolAddress((void**)&Vb, g_V);
    cudaGetSymbolAddress((void**)&Ob, g_AO);

    dim3 blk(256);
    dim3 gProj(DM / 128, TOK / 128);   // (8, 64)

    sgemm_kernel<0, 1><<<gProj, blk>>>(q, Wq, bq, Qb, TOK, DM, DM);
    sgemm_kernel<0, 1><<<gProj, blk>>>(k, Wk, bk, Kb, TOK, DM, DM);
    sgemm_kernel<0, 1><<<gProj, blk>>>(v, Wv, bv, Vb, TOK, DM, DM);

    attn_kernel<<<dim3(SEQ / 64, BHN), blk>>>(Qb, Kb, Vb, Ob);

    sgemm_kernel<1, 0><<<gProj, blk>>>(Ob, Wo, bo, out, TOK, DM, DM);
}

// round 3
// speedup vs baseline: 1.4382x; 1.4382x over previous
#include <cuda_runtime.h>
#include <cstdint>

#define SEQ    2048
#define DM     1024
#define NH     16
#define HD     64
#define BATCH  4
#define BHN    (BATCH * NH)      // 64
#define TOK    (BATCH * SEQ)     // 8192

// Scratch: [B,H,S,hd] layouts, fp32
__device__ float g_Q [(size_t)BHN * SEQ * HD];
__device__ float g_K [(size_t)BHN * SEQ * HD];
__device__ float g_V [(size_t)BHN * SEQ * HD];
__device__ float g_AO[(size_t)BHN * SEQ * HD];

__device__ __forceinline__ uint32_t f2tf32(float x) {
    uint32_t u;
    asm volatile("cvt.rna.tf32.f32 %0, %1;" : "=r"(u) : "f"(x));
    return u;
}

// ---------------------------------------------------------------------------
// tf32 tensor-core GEMM: C[m,n] = sum_k A[m,k] * W[n,k] + bias[n]
// AMODE 0: A row-major [M,K].  AMODE 1: A gathered from [B,H,S,hd] layout.
// OMODE 0: C row-major [M,N].  OMODE 1: C scattered to [B,H,S,hd] layout.
// Tile 128x128x32, 256 threads = 8 warps (2x4), warp tile 64x32,
// mma.sync.m16n8k8.tf32. No smem transposes; stride-36 padding makes the
// STS.128 fill and all scalar fragment LDS conflict-free.
// ---------------------------------------------------------------------------
#define BK   32
#define LDA  36   // padded stride (floats)

template<int AMODE, int OMODE>
__global__ __launch_bounds__(256)
void tgemm_kernel(const float* __restrict__ A, const float* __restrict__ W,
                  const float* __restrict__ bias, float* __restrict__ C,
                  int M, int N, int K)
{
    __shared__ float As[128 * LDA];
    __shared__ float Bs[128 * LDA];

    const int tid  = threadIdx.x;
    const int lane = tid & 31;
    const int warp = tid >> 5;
    const int grp  = lane >> 2;     // 0..7
    const int tig  = lane & 3;      // 0..3
    const int wm   = warp & 1;      // 2 row blocks of 64
    const int wn   = warp >> 1;     // 4 col blocks of 32
    const int rowBase = blockIdx.y * 128;
    const int colBase = blockIdx.x * 128;

    // loader mapping: 32 rows per pass, 4 passes; 8 float4 across BK
    const int lrow = tid >> 3;      // 0..31
    const int lk   = (tid & 7) * 4; // 0,4,...,28

    float acc[4][4][4];
#pragma unroll
    for (int i = 0; i < 4; i++)
#pragma unroll
        for (int j = 0; j < 4; j++)
#pragma unroll
            for (int c = 0; c < 4; c++) acc[i][j][c] = 0.f;

    float4 aReg[4], bReg[4];

    // gmem tile fetch into registers
    auto fetch = [&](int k0) {
#pragma unroll
        for (int p = 0; p < 4; p++) {
            const int r = lrow + p * 32;
            const int kk = k0 + lk;
            const float* ap;
            if (AMODE == 0) {
                ap = A + (size_t)(rowBase + r) * K + kk;
            } else {
                const int m = rowBase + r;
                const int b = m >> 11, s = m & 2047;
                const int h = kk >> 6, d = kk & 63;
                ap = A + (((size_t)(b * NH + h) * SEQ + s) << 6) + d;
            }
            aReg[p] = *(const float4*)ap;
            bReg[p] = *(const float4*)(W + (size_t)(colBase + r) * K + kk);
        }
    };

    auto stage = [&]() {
#pragma unroll
        for (int p = 0; p < 4; p++) {
            const int r = lrow + p * 32;
            uint4 av, bv;
            av.x = f2tf32(aReg[p].x); av.y = f2tf32(aReg[p].y);
            av.z = f2tf32(aReg[p].z); av.w = f2tf32(aReg[p].w);
            bv.x = f2tf32(bReg[p].x); bv.y = f2tf32(bReg[p].y);
            bv.z = f2tf32(bReg[p].z); bv.w = f2tf32(bReg[p].w);
            *(uint4*)&As[r * LDA + lk] = av;
            *(uint4*)&Bs[r * LDA + lk] = bv;
        }
    };

    fetch(0);
    const int ntile = K / BK;
    for (int t = 0; t < ntile; t++) {
        __syncthreads();
        stage();
        __syncthreads();
        if (t + 1 < ntile) fetch((t + 1) * BK);

#pragma unroll
        for (int ks = 0; ks < 4; ks++) {
            const int k = ks * 8;
            uint32_t af[4][4], bf[4][2];
#pragma unroll
            for (int mt = 0; mt < 4; mt++) {
                const int m0 = wm * 64 + mt * 16;
                af[mt][0] = __float_as_uint(As[(m0 + grp)     * LDA + k + tig]);
                af[mt][1] = __float_as_uint(As[(m0 + grp + 8) * LDA + k + tig]);
                af[mt][2] = __float_as_uint(As[(m0 + grp)     * LDA + k + tig + 4]);
                af[mt][3] = __float_as_uint(As[(m0 + grp + 8) * LDA + k + tig + 4]);
            }
#pragma unroll
            for (int nt = 0; nt < 4; nt++) {
                const int n0 = wn * 32 + nt * 8;
                bf[nt][0] = __float_as_uint(Bs[(n0 + grp) * LDA + k + tig]);
                bf[nt][1] = __float_as_uint(Bs[(n0 + grp) * LDA + k + tig + 4]);
            }
#pragma unroll
            for (int mt = 0; mt < 4; mt++)
#pragma unroll
                for (int nt = 0; nt < 4; nt++) {
                    asm volatile(
                        "mma.sync.aligned.m16n8k8.row.col.f32.tf32.tf32.f32 "
                        "{%0,%1,%2,%3}, {%4,%5,%6,%7}, {%8,%9}, {%0,%1,%2,%3};"
                        : "+f"(acc[mt][nt][0]), "+f"(acc[mt][nt][1]),
                          "+f"(acc[mt][nt][2]), "+f"(acc[mt][nt][3])
                        : "r"(af[mt][0]), "r"(af[mt][1]), "r"(af[mt][2]), "r"(af[mt][3]),
                          "r"(bf[nt][0]), "r"(bf[nt][1]));
                }
        }
    }

    // epilogue
#pragma unroll
    for (int mt = 0; mt < 4; mt++) {
#pragma unroll
        for (int half = 0; half < 2; half++) {
            const int m = rowBase + wm * 64 + mt * 16 + grp + half * 8;
            const int b = m >> 11, s = m & 2047;
#pragma unroll
            for (int nt = 0; nt < 4; nt++) {
                const int n = colBase + wn * 32 + nt * 8 + 2 * tig;
                float2 r;
                r.x = acc[mt][nt][half * 2 + 0] + bias[n + 0];
                r.y = acc[mt][nt][half * 2 + 1] + bias[n + 1];
                if (OMODE == 0) {
                    *(float2*)(C + (size_t)m * N + n) = r;
                } else {
                    const int h = n >> 6, d = n & 63;
                    *(float2*)(C + (((size_t)(b * NH + h) * SEQ + s) << 6) + d) = r;
                }
            }
        }
    }
}

// ---------------------------------------------------------------------------
// Flash attention, fp32 (unchanged from R2).
// ---------------------------------------------------------------------------
__global__ __launch_bounds__(256)
void attn_kernel(const float* __restrict__ Qg, const float* __restrict__ Kg,
                 const float* __restrict__ Vg, float* __restrict__ Og)
{
    __shared__ float Qs [64 * 64];
    __shared__ float KPs[64 * 64];
    __shared__ float Vs [64 * 64];

    const int tid = threadIdx.x;
    const int tx  = tid & 15;
    const int ty  = tid >> 4;
    const int bh  = blockIdx.y;
    const int q0  = blockIdx.x * 64;

    const float* Qb = Qg + ((size_t)bh * SEQ + q0) * HD;
    const float* Kb = Kg + (size_t)bh * SEQ * HD;
    const float* Vb = Vg + (size_t)bh * SEQ * HD;

    for (int i = tid; i < 64 * 64; i += 256) {
        const int r = i >> 6, d = i & 63;
        Qs[d * 64 + (r ^ ((d & 15) << 2))] = Qb[i];
    }

    float mi[4], li[4], o[4][4];
#pragma unroll
    for (int i = 0; i < 4; i++) {
        mi[i] = -1e30f; li[i] = 0.f;
#pragma unroll
        for (int j = 0; j < 4; j++) o[i][j] = 0.f;
    }

    for (int kt = 0; kt < SEQ; kt += 64) {
        __syncthreads();
        for (int i = tid; i < 64 * 64; i += 256) {
            const int r = i >> 6, d = i & 63;
            KPs[d * 64 + (r ^ ((d & 15) << 2))] = Kb[(size_t)kt * HD + i];
            Vs[i] = Vb[(size_t)kt * HD + i];
        }
        __syncthreads();

        float s[4][4];
#pragma unroll
        for (int i = 0; i < 4; i++)
#pragma unroll
            for (int j = 0; j < 4; j++) s[i][j] = 0.f;

#pragma unroll 16
        for (int d = 0; d < 64; d++) {
            const int sw = (d & 15) << 2;
            float4 qa = *(const float4*)&Qs [d * 64 + ((4 * ty) ^ sw)];
            float4 kb = *(const float4*)&KPs[d * 64 + ((4 * tx) ^ sw)];
            float qr[4] = {qa.x, qa.y, qa.z, qa.w};
            float kr[4] = {kb.x, kb.y, kb.z, kb.w};
#pragma unroll
            for (int i = 0; i < 4; i++)
#pragma unroll
                for (int j = 0; j < 4; j++)
                    s[i][j] = fmaf(qr[i], kr[j], s[i][j]);
        }

        float alpha[4];
#pragma unroll
        for (int i = 0; i < 4; i++) {
#pragma unroll
            for (int j = 0; j < 4; j++) s[i][j] *= 0.125f;
            float r = fmaxf(fmaxf(s[i][0], s[i][1]), fmaxf(s[i][2], s[i][3]));
            r = fmaxf(r, __shfl_xor_sync(0xffffffffu, r, 1));
            r = fmaxf(r, __shfl_xor_sync(0xffffffffu, r, 2));
            r = fmaxf(r, __shfl_xor_sync(0xffffffffu, r, 4));
            r = fmaxf(r, __shfl_xor_sync(0xffffffffu, r, 8));
            const float mnew = fmaxf(mi[i], r);
            alpha[i] = __expf(mi[i] - mnew);
            float rs = 0.f;
#pragma unroll
            for (int j = 0; j < 4; j++) {
                s[i][j] = __expf(s[i][j] - mnew);
                rs += s[i][j];
            }
            rs += __shfl_xor_sync(0xffffffffu, rs, 1);
            rs += __shfl_xor_sync(0xffffffffu, rs, 2);
            rs += __shfl_xor_sync(0xffffffffu, rs, 4);
            rs += __shfl_xor_sync(0xffffffffu, rs, 8);
            li[i] = li[i] * alpha[i] + rs;
            mi[i] = mnew;
#pragma unroll
            for (int j = 0; j < 4; j++) o[i][j] *= alpha[i];
        }

        __syncthreads();
#pragma unroll
        for (int i = 0; i < 4; i++) {
            float4 p = make_float4(s[i][0], s[i][1], s[i][2], s[i][3]);
            *(float4*)&KPs[(4 * ty + i) * 64 + 4 * tx] = p;
        }
        __syncthreads();

#pragma unroll 4
        for (int k4 = 0; k4 < 64; k4 += 4) {
            float4 p4[4];
#pragma unroll
            for (int i = 0; i < 4; i++)
                p4[i] = *(const float4*)&KPs[(4 * ty + i) * 64 + k4];
#pragma unroll
            for (int kk = 0; kk < 4; kk++) {
                float4 vv = *(const float4*)&Vs[(k4 + kk) * 64 + 4 * tx];
                float vr[4] = {vv.x, vv.y, vv.z, vv.w};
                float pr[4] = {kk == 0 ? p4[0].x : kk == 1 ? p4[0].y : kk == 2 ? p4[0].z : p4[0].w,
                               kk == 0 ? p4[1].x : kk == 1 ? p4[1].y : kk == 2 ? p4[1].z : p4[1].w,
                               kk == 0 ? p4[2].x : kk == 1 ? p4[2].y : kk == 2 ? p4[2].z : p4[2].w,
                               kk == 0 ? p4[3].x : kk == 1 ? p4[3].y : kk == 2 ? p4[3].z : p4[3].w};
#pragma unroll
                for (int i = 0; i < 4; i++)
#pragma unroll
                    for (int j = 0; j < 4; j++)
                        o[i][j] = fmaf(pr[i], vr[j], o[i][j]);
            }
        }
    }

    float* Ob = Og + ((size_t)bh * SEQ + q0) * HD;
#pragma unroll
    for (int i = 0; i < 4; i++) {
        const float inv = 1.0f / li[i];
        float4 r = make_float4(o[i][0] * inv, o[i][1] * inv, o[i][2] * inv, o[i][3] * inv);
        *(float4*)&Ob[(4 * ty + i) * 64 + 4 * tx] = r;
    }
}

// ---------------------------------------------------------------------------
extern "C" void kernel_launch(void* const* d_in, const int* in_sizes, int n_in,
                              void* d_out, int out_size)
{
    const float* q  = (const float*)d_in[0];
    const float* k  = (const float*)d_in[1];
    const float* v  = (const float*)d_in[2];
    const float* Wq = (const float*)d_in[3];
    const float* bq = (const float*)d_in[4];
    const float* Wk = (const float*)d_in[5];
    const float* bk = (const float*)d_in[6];
    const float* Wv = (const float*)d_in[7];
    const float* bv = (const float*)d_in[8];
    const float* Wo = (const float*)d_in[9];
    const float* bo = (const float*)d_in[10];
    float* out = (float*)d_out;

    float *Qb, *Kb, *Vb, *Ob;
    cudaGetSymbolAddress((void**)&Qb, g_Q);
    cudaGetSymbolAddress((void**)&Kb, g_K);
    cudaGetSymbolAddress((void**)&Vb, g_V);
    cudaGetSymbolAddress((void**)&Ob, g_AO);

    dim3 blk(256);
    dim3 gProj(DM / 128, TOK / 128);   // (8, 64)

    tgemm_kernel<0, 1><<<gProj, blk>>>(q, Wq, bq, Qb, TOK, DM, DM);
    tgemm_kernel<0, 1><<<gProj, blk>>>(k, Wk, bk, Kb, TOK, DM, DM);
    tgemm_kernel<0, 1><<<gProj, blk>>>(v, Wv, bv, Vb, TOK, DM, DM);

    attn_kernel<<<dim3(SEQ / 64, BHN), blk>>>(Qb, Kb, Vb, Ob);

    tgemm_kernel<1, 0><<<gProj, blk>>>(Ob, Wo, bo, out, TOK, DM, DM);
}

// round 5
// speedup vs baseline: 1.9074x; 1.3262x over previous
#include <cuda_runtime.h>
#include <cstdint>

#define SEQ    2048
#define DM     1024
#define NH     16
#define HD     64
#define BATCH  4
#define BHN    (BATCH * NH)      // 64
#define TOK    (BATCH * SEQ)     // 8192

// Scratch: [B,H,S,hd] layouts, fp32
__device__ float g_Q [(size_t)BHN * SEQ * HD];
__device__ float g_K [(size_t)BHN * SEQ * HD];
__device__ float g_V [(size_t)BHN * SEQ * HD];
__device__ float g_AO[(size_t)BHN * SEQ * HD];

__device__ __forceinline__ uint32_t f2tf32(float x) {
    uint32_t u;
    asm volatile("cvt.rna.tf32.f32 %0, %1;" : "=r"(u) : "f"(x));
    return u;
}

__device__ __forceinline__ void mma_tf32(float c[4], const uint32_t a[4], const uint32_t b[2]) {
    asm volatile(
        "mma.sync.aligned.m16n8k8.row.col.f32.tf32.tf32.f32 "
        "{%0,%1,%2,%3}, {%4,%5,%6,%7}, {%8,%9}, {%0,%1,%2,%3};"
        : "+f"(c[0]), "+f"(c[1]), "+f"(c[2]), "+f"(c[3])
        : "r"(a[0]), "r"(a[1]), "r"(a[2]), "r"(a[3]), "r"(b[0]), "r"(b[1]));
}

// ---------------------------------------------------------------------------
// tf32 tensor-core GEMM (unchanged, proven in R3)
// ---------------------------------------------------------------------------
#define BK   32
#define LDA  36

template<int AMODE, int OMODE>
__global__ __launch_bounds__(256)
void tgemm_kernel(const float* __restrict__ A, const float* __restrict__ W,
                  const float* __restrict__ bias, float* __restrict__ C,
                  int M, int N, int K)
{
    __shared__ float As[128 * LDA];
    __shared__ float Bs[128 * LDA];

    const int tid  = threadIdx.x;
    const int lane = tid & 31;
    const int warp = tid >> 5;
    const int grp  = lane >> 2;
    const int tig  = lane & 3;
    const int wm   = warp & 1;
    const int wn   = warp >> 1;
    const int rowBase = blockIdx.y * 128;
    const int colBase = blockIdx.x * 128;

    const int lrow = tid >> 3;
    const int lk   = (tid & 7) * 4;

    float acc[4][4][4];
#pragma unroll
    for (int i = 0; i < 4; i++)
#pragma unroll
        for (int j = 0; j < 4; j++)
#pragma unroll
            for (int c = 0; c < 4; c++) acc[i][j][c] = 0.f;

    float4 aReg[4], bReg[4];

    auto fetch = [&](int k0) {
#pragma unroll
        for (int p = 0; p < 4; p++) {
            const int r = lrow + p * 32;
            const int kk = k0 + lk;
            const float* ap;
            if (AMODE == 0) {
                ap = A + (size_t)(rowBase + r) * K + kk;
            } else {
                const int m = rowBase + r;
                const int b = m >> 11, s = m & 2047;
                const int h = kk >> 6, d = kk & 63;
                ap = A + (((size_t)(b * NH + h) * SEQ + s) << 6) + d;
            }
            aReg[p] = *(const float4*)ap;
            bReg[p] = *(const float4*)(W + (size_t)(colBase + r) * K + kk);
        }
    };

    auto stage = [&]() {
#pragma unroll
        for (int p = 0; p < 4; p++) {
            const int r = lrow + p * 32;
            uint4 av, bv;
            av.x = f2tf32(aReg[p].x); av.y = f2tf32(aReg[p].y);
            av.z = f2tf32(aReg[p].z); av.w = f2tf32(aReg[p].w);
            bv.x = f2tf32(bReg[p].x); bv.y = f2tf32(bReg[p].y);
            bv.z = f2tf32(bReg[p].z); bv.w = f2tf32(bReg[p].w);
            *(uint4*)&As[r * LDA + lk] = av;
            *(uint4*)&Bs[r * LDA + lk] = bv;
        }
    };

    fetch(0);
    const int ntile = K / BK;
    for (int t = 0; t < ntile; t++) {
        __syncthreads();
        stage();
        __syncthreads();
        if (t + 1 < ntile) fetch((t + 1) * BK);

#pragma unroll
        for (int ks = 0; ks < 4; ks++) {
            const int k = ks * 8;
            uint32_t af[4][4], bf[4][2];
#pragma unroll
            for (int mt = 0; mt < 4; mt++) {
                const int m0 = wm * 64 + mt * 16;
                af[mt][0] = __float_as_uint(As[(m0 + grp)     * LDA + k + tig]);
                af[mt][1] = __float_as_uint(As[(m0 + grp + 8) * LDA + k + tig]);
                af[mt][2] = __float_as_uint(As[(m0 + grp)     * LDA + k + tig + 4]);
                af[mt][3] = __float_as_uint(As[(m0 + grp + 8) * LDA + k + tig + 4]);
            }
#pragma unroll
            for (int nt = 0; nt < 4; nt++) {
                const int n0 = wn * 32 + nt * 8;
                bf[nt][0] = __float_as_uint(Bs[(n0 + grp) * LDA + k + tig]);
                bf[nt][1] = __float_as_uint(Bs[(n0 + grp) * LDA + k + tig + 4]);
            }
#pragma unroll
            for (int mt = 0; mt < 4; mt++)
#pragma unroll
                for (int nt = 0; nt < 4; nt++)
                    mma_tf32(acc[mt][nt], af[mt], bf[nt]);
        }
    }

#pragma unroll
    for (int mt = 0; mt < 4; mt++) {
#pragma unroll
        for (int half = 0; half < 2; half++) {
            const int m = rowBase + wm * 64 + mt * 16 + grp + half * 8;
            const int b = m >> 11, s = m & 2047;
#pragma unroll
            for (int nt = 0; nt < 4; nt++) {
                const int n = colBase + wn * 32 + nt * 8 + 2 * tig;
                float2 r;
                r.x = acc[mt][nt][half * 2 + 0] + bias[n + 0];
                r.y = acc[mt][nt][half * 2 + 1] + bias[n + 1];
                if (OMODE == 0) {
                    *(float2*)(C + (size_t)m * N + n) = r;
                } else {
                    const int h = n >> 6, d = n & 63;
                    *(float2*)(C + (((size_t)(b * NH + h) * SEQ + s) << 6) + d) = r;
                }
            }
        }
    }
}

// ---------------------------------------------------------------------------
// Tensor-core flash attention, warp-owns-full-rows layout.
// BM=128 q rows per CTA; 8 warps, warp w owns rows w*16..w*16+15 and ALL
// 64 columns (S: m16 x n64, O: m16 x d64) -> softmax is warp-local.
// One-sided hi/lo splits: K split (QK^T), P split (PV); Q,V plain tf32.
// Stride-68 smem: all fragment LDS conflict-free.
// ---------------------------------------------------------------------------
#define ALD 68
#define SM_KH   0                      // K_hi 64*68
#define SM_KL   (64 * ALD)             // K_lo
#define SM_V    (2 * 64 * ALD)         // V (tf32)
#define SM_PH   (3 * 64 * ALD)         // P_hi 128*68 (also Q staging)
#define SM_PL   (3 * 64 * ALD + 128 * ALD)
#define ATTN_SMEM_FLOATS (3 * 64 * ALD + 2 * 128 * ALD)
#define ATTN_SMEM_BYTES  (ATTN_SMEM_FLOATS * 4)

__global__ __launch_bounds__(256)
void attn_tc_kernel(const float* __restrict__ Qg, const float* __restrict__ Kg,
                    const float* __restrict__ Vg, float* __restrict__ Og)
{
    extern __shared__ float smem[];
    float* Ks_hi = smem + SM_KH;
    float* Ks_lo = smem + SM_KL;
    float* Vs    = smem + SM_V;
    float* Ps_hi = smem + SM_PH;
    float* Ps_lo = smem + SM_PL;

    const int tid  = threadIdx.x;
    const int lane = tid & 31;
    const int warp = tid >> 5;
    const int grp  = lane >> 2;
    const int tig  = lane & 3;
    const int m0   = warp * 16;      // warp's 16 rows
    const int bh   = blockIdx.y;
    const int q0   = blockIdx.x * 128;

    const float* Qb = Qg + ((size_t)bh * SEQ + q0) * HD;
    const float* Kb = Kg + (size_t)bh * SEQ * HD;
    const float* Vb = Vg + (size_t)bh * SEQ * HD;

    // ---- stage Q into Ps_hi, then build Q fragments (scale folded in) ----
    for (int i = tid; i < 128 * 16; i += 256) {
        const int c4 = i & 15, r = i >> 4;
        *(float4*)&Ps_hi[r * ALD + c4 * 4] = *(const float4*)(Qb + r * HD + c4 * 4);
    }
    __syncthreads();

    uint32_t qa[8][4];
#pragma unroll
    for (int ks = 0; ks < 8; ks++) {
        qa[ks][0] = f2tf32(0.125f * Ps_hi[(m0 + grp)     * ALD + ks * 8 + tig]);
        qa[ks][1] = f2tf32(0.125f * Ps_hi[(m0 + grp + 8) * ALD + ks * 8 + tig]);
        qa[ks][2] = f2tf32(0.125f * Ps_hi[(m0 + grp)     * ALD + ks * 8 + tig + 4]);
        qa[ks][3] = f2tf32(0.125f * Ps_hi[(m0 + grp + 8) * ALD + ks * 8 + tig + 4]);
    }

    float o[8][4];
    float mi[2], li[2];
    mi[0] = mi[1] = -1e30f; li[0] = li[1] = 0.f;
#pragma unroll
    for (int nt = 0; nt < 8; nt++)
#pragma unroll
        for (int c = 0; c < 4; c++) o[nt][c] = 0.f;

    for (int kt = 0; kt < SEQ; kt += 64) {
        __syncthreads();   // all warps done with Ks/Vs from previous tile
        for (int i = tid; i < 64 * 16; i += 256) {
            const int c4 = i & 15, r = i >> 4;
            float4 k4 = *(const float4*)(Kb + (size_t)(kt + r) * HD + c4 * 4);
            uint4 h, l;
            h.x = f2tf32(k4.x); l.x = f2tf32(k4.x - __uint_as_float(h.x));
            h.y = f2tf32(k4.y); l.y = f2tf32(k4.y - __uint_as_float(h.y));
            h.z = f2tf32(k4.z); l.z = f2tf32(k4.z - __uint_as_float(h.z));
            h.w = f2tf32(k4.w); l.w = f2tf32(k4.w - __uint_as_float(h.w));
            *(uint4*)&Ks_hi[r * ALD + c4 * 4] = h;
            *(uint4*)&Ks_lo[r * ALD + c4 * 4] = l;
            float4 v4 = *(const float4*)(Vb + (size_t)(kt + r) * HD + c4 * 4);
            uint4 vv;
            vv.x = f2tf32(v4.x); vv.y = f2tf32(v4.y);
            vv.z = f2tf32(v4.z); vv.w = f2tf32(v4.w);
            *(uint4*)&Vs[r * ALD + c4 * 4] = vv;
        }
        __syncthreads();

        // ---- S = Q*(K_hi + K_lo)^T : warp tile m16 x n64 ----
        float s[8][4];
#pragma unroll
        for (int nt = 0; nt < 8; nt++)
#pragma unroll
            for (int c = 0; c < 4; c++) s[nt][c] = 0.f;

#pragma unroll
        for (int ks = 0; ks < 8; ks++) {
#pragma unroll
            for (int nt = 0; nt < 8; nt++) {
                const int n = nt * 8 + grp;
                uint32_t bh2[2], bl2[2];
                bh2[0] = __float_as_uint(Ks_hi[n * ALD + ks * 8 + tig]);
                bh2[1] = __float_as_uint(Ks_hi[n * ALD + ks * 8 + tig + 4]);
                bl2[0] = __float_as_uint(Ks_lo[n * ALD + ks * 8 + tig]);
                bl2[1] = __float_as_uint(Ks_lo[n * ALD + ks * 8 + tig + 4]);
                mma_tf32(s[nt], qa[ks], bh2);
                mma_tf32(s[nt], qa[ks], bl2);
            }
        }

        // ---- online softmax: rows grp+8h fully within warp ----
        float alpha[2];
#pragma unroll
        for (int h = 0; h < 2; h++) {
            float mx = -1e30f;
#pragma unroll
            for (int nt = 0; nt < 8; nt++)
                mx = fmaxf(mx, fmaxf(s[nt][2 * h], s[nt][2 * h + 1]));
            mx = fmaxf(mx, __shfl_xor_sync(0xffffffffu, mx, 1));
            mx = fmaxf(mx, __shfl_xor_sync(0xffffffffu, mx, 2));
            const float mnew = fmaxf(mi[h], mx);
            alpha[h] = __expf(mi[h] - mnew);
            float rs = 0.f;
#pragma unroll
            for (int nt = 0; nt < 8; nt++) {
                s[nt][2 * h]     = __expf(s[nt][2 * h]     - mnew);
                s[nt][2 * h + 1] = __expf(s[nt][2 * h + 1] - mnew);
                rs += s[nt][2 * h] + s[nt][2 * h + 1];
            }
            rs += __shfl_xor_sync(0xffffffffu, rs, 1);
            rs += __shfl_xor_sync(0xffffffffu, rs, 2);
            li[h] = li[h] * alpha[h] + rs;
            mi[h] = mnew;
        }
#pragma unroll
        for (int nt = 0; nt < 8; nt++)
#pragma unroll
            for (int c = 0; c < 4; c++)
                o[nt][c] *= alpha[c >> 1];

        // ---- store P hi/lo (warp-private rows) ----
#pragma unroll
        for (int h = 0; h < 2; h++) {
            const int row = m0 + grp + 8 * h;
#pragma unroll
            for (int nt = 0; nt < 8; nt++) {
                const int col = nt * 8 + 2 * tig;
                const float p0 = s[nt][2 * h], p1 = s[nt][2 * h + 1];
                uint2 ph, pl;
                ph.x = f2tf32(p0); pl.x = f2tf32(p0 - __uint_as_float(ph.x));
                ph.y = f2tf32(p1); pl.y = f2tf32(p1 - __uint_as_float(ph.y));
                *(uint2*)&Ps_hi[row * ALD + col] = ph;
                *(uint2*)&Ps_lo[row * ALD + col] = pl;
            }
        }
        __syncwarp();   // only this warp reads its rows back

        // ---- O += (P_hi + P_lo) * V : warp tile m16 x d64 ----
#pragma unroll
        for (int ks = 0; ks < 8; ks++) {
            uint32_t ah[4], al[4];
            ah[0] = __float_as_uint(Ps_hi[(m0 + grp)     * ALD + ks * 8 + tig]);
            ah[1] = __float_as_uint(Ps_hi[(m0 + grp + 8) * ALD + ks * 8 + tig]);
            ah[2] = __float_as_uint(Ps_hi[(m0 + grp)     * ALD + ks * 8 + tig + 4]);
            ah[3] = __float_as_uint(Ps_hi[(m0 + grp + 8) * ALD + ks * 8 + tig + 4]);
            al[0] = __float_as_uint(Ps_lo[(m0 + grp)     * ALD + ks * 8 + tig]);
            al[1] = __float_as_uint(Ps_lo[(m0 + grp + 8) * ALD + ks * 8 + tig]);
            al[2] = __float_as_uint(Ps_lo[(m0 + grp)     * ALD + ks * 8 + tig + 4]);
            al[3] = __float_as_uint(Ps_lo[(m0 + grp + 8) * ALD + ks * 8 + tig + 4]);
#pragma unroll
            for (int nt = 0; nt < 8; nt++) {
                const int d = nt * 8 + grp;
                uint32_t bv2[2];
                bv2[0] = __float_as_uint(Vs[(ks * 8 + tig)     * ALD + d]);
                bv2[1] = __float_as_uint(Vs[(ks * 8 + tig + 4) * ALD + d]);
                mma_tf32(o[nt], ah, bv2);
                mma_tf32(o[nt], al, bv2);
            }
        }
    }

    // ---- epilogue ----
    float* Ob = Og + ((size_t)bh * SEQ + q0) * HD;
#pragma unroll
    for (int h = 0; h < 2; h++) {
        const int row = m0 + grp + 8 * h;
        const float inv = 1.0f / li[h];
#pragma unroll
        for (int nt = 0; nt < 8; nt++) {
            const int d = nt * 8 + 2 * tig;
            float2 r;
            r.x = o[nt][2 * h]     * inv;
            r.y = o[nt][2 * h + 1] * inv;
            *(float2*)&Ob[(size_t)row * HD + d] = r;
        }
    }
}

// ---------------------------------------------------------------------------
extern "C" void kernel_launch(void* const* d_in, const int* in_sizes, int n_in,
                              void* d_out, int out_size)
{
    const float* q  = (const float*)d_in[0];
    const float* k  = (const float*)d_in[1];
    const float* v  = (const float*)d_in[2];
    const float* Wq = (const float*)d_in[3];
    const float* bq = (const float*)d_in[4];
    const float* Wk = (const float*)d_in[5];
    const float* bk = (const float*)d_in[6];
    const float* Wv = (const float*)d_in[7];
    const float* bv = (const float*)d_in[8];
    const float* Wo = (const float*)d_in[9];
    const float* bo = (const float*)d_in[10];
    float* out = (float*)d_out;

    float *Qb, *Kb, *Vb, *Ob;
    cudaGetSymbolAddress((void**)&Qb, g_Q);
    cudaGetSymbolAddress((void**)&Kb, g_K);
    cudaGetSymbolAddress((void**)&Vb, g_V);
    cudaGetSymbolAddress((void**)&Ob, g_AO);

    cudaFuncSetAttribute(attn_tc_kernel,
                         cudaFuncAttributeMaxDynamicSharedMemorySize, ATTN_SMEM_BYTES);

    dim3 blk(256);
    dim3 gProj(DM / 128, TOK / 128);   // (8, 64)

    tgemm_kernel<0, 1><<<gProj, blk>>>(q, Wq, bq, Qb, TOK, DM, DM);
    tgemm_kernel<0, 1><<<gProj, blk>>>(k, Wk, bk, Kb, TOK, DM, DM);
    tgemm_kernel<0, 1><<<gProj, blk>>>(v, Wv, bv, Vb, TOK, DM, DM);

    attn_tc_kernel<<<dim3(SEQ / 128, BHN), blk, ATTN_SMEM_BYTES>>>(Qb, Kb, Vb, Ob);

    tgemm_kernel<1, 0><<<gProj, blk>>>(Ob, Wo, bo, out, TOK, DM, DM);
}

// round 6
// speedup vs baseline: 2.3645x; 1.2397x over previous
#include <cuda_runtime.h>
#include <cstdint>

#define SEQ    2048
#define DM     1024
#define NH     16
#define HD     64
#define BATCH  4
#define BHN    (BATCH * NH)      // 64
#define TOK    (BATCH * SEQ)     // 8192

// Scratch: [B,H,S,hd] layouts, fp32
__device__ float g_Q [(size_t)BHN * SEQ * HD];
__device__ float g_K [(size_t)BHN * SEQ * HD];
__device__ float g_V [(size_t)BHN * SEQ * HD];
__device__ float g_AO[(size_t)BHN * SEQ * HD];

__device__ __forceinline__ uint32_t f2tf32(float x) {
    uint32_t u;
    asm volatile("cvt.rna.tf32.f32 %0, %1;" : "=r"(u) : "f"(x));
    return u;
}

__device__ __forceinline__ void mma_tf32(float c[4], const uint32_t a[4], const uint32_t b[2]) {
    asm volatile(
        "mma.sync.aligned.m16n8k8.row.col.f32.tf32.tf32.f32 "
        "{%0,%1,%2,%3}, {%4,%5,%6,%7}, {%8,%9}, {%0,%1,%2,%3};"
        : "+f"(c[0]), "+f"(c[1]), "+f"(c[2]), "+f"(c[3])
        : "r"(a[0]), "r"(a[1]), "r"(a[2]), "r"(a[3]), "r"(b[0]), "r"(b[1]));
}

__device__ __forceinline__ void cp16(float* dst, const float* src) {
    asm volatile("cp.async.cg.shared.global [%0], [%1], 16;"
                 :: "r"((uint32_t)__cvta_generic_to_shared(dst)), "l"(src));
}
__device__ __forceinline__ void cp_commit() {
    asm volatile("cp.async.commit_group;");
}
template<int N>
__device__ __forceinline__ void cp_wait() {
    asm volatile("cp.async.wait_group %0;" :: "n"(N));
}

// ---------------------------------------------------------------------------
// tf32 tensor-core GEMM (unchanged, proven in R3)
// ---------------------------------------------------------------------------
#define BK   32
#define LDA  36

template<int AMODE, int OMODE>
__global__ __launch_bounds__(256)
void tgemm_kernel(const float* __restrict__ A, const float* __restrict__ W,
                  const float* __restrict__ bias, float* __restrict__ C,
                  int M, int N, int K)
{
    __shared__ float As[128 * LDA];
    __shared__ float Bs[128 * LDA];

    const int tid  = threadIdx.x;
    const int lane = tid & 31;
    const int warp = tid >> 5;
    const int grp  = lane >> 2;
    const int tig  = lane & 3;
    const int wm   = warp & 1;
    const int wn   = warp >> 1;
    const int rowBase = blockIdx.y * 128;
    const int colBase = blockIdx.x * 128;

    const int lrow = tid >> 3;
    const int lk   = (tid & 7) * 4;

    float acc[4][4][4];
#pragma unroll
    for (int i = 0; i < 4; i++)
#pragma unroll
        for (int j = 0; j < 4; j++)
#pragma unroll
            for (int c = 0; c < 4; c++) acc[i][j][c] = 0.f;

    float4 aReg[4], bReg[4];

    auto fetch = [&](int k0) {
#pragma unroll
        for (int p = 0; p < 4; p++) {
            const int r = lrow + p * 32;
            const int kk = k0 + lk;
            const float* ap;
            if (AMODE == 0) {
                ap = A + (size_t)(rowBase + r) * K + kk;
            } else {
                const int m = rowBase + r;
                const int b = m >> 11, s = m & 2047;
                const int h = kk >> 6, d = kk & 63;
                ap = A + (((size_t)(b * NH + h) * SEQ + s) << 6) + d;
            }
            aReg[p] = *(const float4*)ap;
            bReg[p] = *(const float4*)(W + (size_t)(colBase + r) * K + kk);
        }
    };

    auto stage = [&]() {
#pragma unroll
        for (int p = 0; p < 4; p++) {
            const int r = lrow + p * 32;
            uint4 av, bv;
            av.x = f2tf32(aReg[p].x); av.y = f2tf32(aReg[p].y);
            av.z = f2tf32(aReg[p].z); av.w = f2tf32(aReg[p].w);
            bv.x = f2tf32(bReg[p].x); bv.y = f2tf32(bReg[p].y);
            bv.z = f2tf32(bReg[p].z); bv.w = f2tf32(bReg[p].w);
            *(uint4*)&As[r * LDA + lk] = av;
            *(uint4*)&Bs[r * LDA + lk] = bv;
        }
    };

    fetch(0);
    const int ntile = K / BK;
    for (int t = 0; t < ntile; t++) {
        __syncthreads();
        stage();
        __syncthreads();
        if (t + 1 < ntile) fetch((t + 1) * BK);

#pragma unroll
        for (int ks = 0; ks < 4; ks++) {
            const int k = ks * 8;
            uint32_t af[4][4], bf[4][2];
#pragma unroll
            for (int mt = 0; mt < 4; mt++) {
                const int m0 = wm * 64 + mt * 16;
                af[mt][0] = __float_as_uint(As[(m0 + grp)     * LDA + k + tig]);
                af[mt][1] = __float_as_uint(As[(m0 + grp + 8) * LDA + k + tig]);
                af[mt][2] = __float_as_uint(As[(m0 + grp)     * LDA + k + tig + 4]);
                af[mt][3] = __float_as_uint(As[(m0 + grp + 8) * LDA + k + tig + 4]);
            }
#pragma unroll
            for (int nt = 0; nt < 4; nt++) {
                const int n0 = wn * 32 + nt * 8;
                bf[nt][0] = __float_as_uint(Bs[(n0 + grp) * LDA + k + tig]);
                bf[nt][1] = __float_as_uint(Bs[(n0 + grp) * LDA + k + tig + 4]);
            }
#pragma unroll
            for (int mt = 0; mt < 4; mt++)
#pragma unroll
                for (int nt = 0; nt < 4; nt++)
                    mma_tf32(acc[mt][nt], af[mt], bf[nt]);
        }
    }

#pragma unroll
    for (int mt = 0; mt < 4; mt++) {
#pragma unroll
        for (int half = 0; half < 2; half++) {
            const int m = rowBase + wm * 64 + mt * 16 + grp + half * 8;
            const int b = m >> 11, s = m & 2047;
#pragma unroll
            for (int nt = 0; nt < 4; nt++) {
                const int n = colBase + wn * 32 + nt * 8 + 2 * tig;
                float2 r;
                r.x = acc[mt][nt][half * 2 + 0] + bias[n + 0];
                r.y = acc[mt][nt][half * 2 + 1] + bias[n + 1];
                if (OMODE == 0) {
                    *(float2*)(C + (size_t)m * N + n) = r;
                } else {
                    const int h = n >> 6, d = n & 63;
                    *(float2*)(C + (((size_t)(b * NH + h) * SEQ + s) << 6) + d) = r;
                }
            }
        }
    }
}

// ---------------------------------------------------------------------------
// Tensor-core flash attention v2:
//  - BM=64 q rows per CTA, 128 threads (4 warps x 16 rows); softmax warp-local
//  - cp.async 2-stage double buffer for raw fp32 K and V tiles
//  - K hi/lo split and V tf32 cvt done at fragment-load time (registers)
//  - P stored plain tf32 (one-sided split only on K); smem 85KB -> 2 CTA/SM
// ---------------------------------------------------------------------------
#define ALD 68
#define AT_K(buf)  ((buf) * (64 * ALD))                 // Kbuf[2]
#define AT_V(buf)  ((2 + (buf)) * (64 * ALD))           // Vbuf[2]
#define AT_P       (4 * (64 * ALD))                     // P / Q staging
#define ATTN_SMEM_FLOATS (5 * 64 * ALD)
#define ATTN_SMEM_BYTES  (ATTN_SMEM_FLOATS * 4)         // 87040 B

__global__ __launch_bounds__(128)
void attn_tc_kernel(const float* __restrict__ Qg, const float* __restrict__ Kg,
                    const float* __restrict__ Vg, float* __restrict__ Og)
{
    extern __shared__ float smem[];
    float* Ps = smem + AT_P;

    const int tid  = threadIdx.x;
    const int lane = tid & 31;
    const int warp = tid >> 5;
    const int grp  = lane >> 2;
    const int tig  = lane & 3;
    const int m0   = warp * 16;          // warp's 16 rows
    const int bh   = blockIdx.y;
    const int q0   = blockIdx.x * 64;

    const float* Qb = Qg + ((size_t)bh * SEQ + q0) * HD;
    const float* Kb = Kg + (size_t)bh * SEQ * HD;
    const float* Vb = Vg + (size_t)bh * SEQ * HD;

    // ---- prefetch kv tile 0 ----
    {
        float* Kd = smem + AT_K(0);
        float* Vd = smem + AT_V(0);
        for (int i = tid; i < 64 * 16; i += 128) {
            const int r = i >> 4, c4 = (i & 15) * 4;
            cp16(&Kd[r * ALD + c4], Kb + (size_t)r * HD + c4);
            cp16(&Vd[r * ALD + c4], Vb + (size_t)r * HD + c4);
        }
        cp_commit();
    }

    // ---- stage Q into Ps, build Q fragments (0.125 scale folded) ----
    for (int i = tid; i < 64 * 16; i += 128) {
        const int r = i >> 4, c4 = (i & 15) * 4;
        *(float4*)&Ps[r * ALD + c4] = *(const float4*)(Qb + (size_t)r * HD + c4);
    }
    __syncthreads();

    uint32_t qa[8][4];
#pragma unroll
    for (int ks = 0; ks < 8; ks++) {
        qa[ks][0] = f2tf32(0.125f * Ps[(m0 + grp)     * ALD + ks * 8 + tig]);
        qa[ks][1] = f2tf32(0.125f * Ps[(m0 + grp + 8) * ALD + ks * 8 + tig]);
        qa[ks][2] = f2tf32(0.125f * Ps[(m0 + grp)     * ALD + ks * 8 + tig + 4]);
        qa[ks][3] = f2tf32(0.125f * Ps[(m0 + grp + 8) * ALD + ks * 8 + tig + 4]);
    }
    __syncthreads();   // all warps done reading Q staging before P overwrites

    float o[8][4];
    float mi[2], li[2];
    mi[0] = mi[1] = -1e30f; li[0] = li[1] = 0.f;
#pragma unroll
    for (int nt = 0; nt < 8; nt++)
#pragma unroll
        for (int c = 0; c < 4; c++) o[nt][c] = 0.f;

    const int NT = SEQ / 64;   // 32
    for (int t = 0; t < NT; t++) {
        const int cur = t & 1;
        // prefetch next tile into other buffer
        if (t + 1 < NT) {
            float* Kd = smem + AT_K(1 - cur);
            float* Vd = smem + AT_V(1 - cur);
            const size_t off = (size_t)(t + 1) * 64 * HD;
            for (int i = tid; i < 64 * 16; i += 128) {
                const int r = i >> 4, c4 = (i & 15) * 4;
                cp16(&Kd[r * ALD + c4], Kb + off + (size_t)r * HD + c4);
                cp16(&Vd[r * ALD + c4], Vb + off + (size_t)r * HD + c4);
            }
            cp_commit();
            cp_wait<1>();
        } else {
            cp_wait<0>();
        }
        __syncthreads();   // tile t visible to all warps

        const float* Ks = smem + AT_K(cur);
        const float* Vs = smem + AT_V(cur);

        // ---- S = Q * (K_hi + K_lo)^T, split computed on the fly ----
        float s[8][4];
#pragma unroll
        for (int nt = 0; nt < 8; nt++)
#pragma unroll
            for (int c = 0; c < 4; c++) s[nt][c] = 0.f;

#pragma unroll
        for (int ks = 0; ks < 8; ks++) {
#pragma unroll
            for (int nt = 0; nt < 8; nt++) {
                const int n = nt * 8 + grp;
                const float k0 = Ks[n * ALD + ks * 8 + tig];
                const float k1 = Ks[n * ALD + ks * 8 + tig + 4];
                uint32_t bh2[2], bl2[2];
                bh2[0] = f2tf32(k0); bl2[0] = f2tf32(k0 - __uint_as_float(bh2[0]));
                bh2[1] = f2tf32(k1); bl2[1] = f2tf32(k1 - __uint_as_float(bh2[1]));
                mma_tf32(s[nt], qa[ks], bh2);
                mma_tf32(s[nt], qa[ks], bl2);
            }
        }

        // ---- online softmax (warp-local rows) ----
        float alpha[2];
#pragma unroll
        for (int h = 0; h < 2; h++) {
            float mx = -1e30f;
#pragma unroll
            for (int nt = 0; nt < 8; nt++)
                mx = fmaxf(mx, fmaxf(s[nt][2 * h], s[nt][2 * h + 1]));
            mx = fmaxf(mx, __shfl_xor_sync(0xffffffffu, mx, 1));
            mx = fmaxf(mx, __shfl_xor_sync(0xffffffffu, mx, 2));
            const float mnew = fmaxf(mi[h], mx);
            alpha[h] = __expf(mi[h] - mnew);
            float rs = 0.f;
#pragma unroll
            for (int nt = 0; nt < 8; nt++) {
                s[nt][2 * h]     = __expf(s[nt][2 * h]     - mnew);
                s[nt][2 * h + 1] = __expf(s[nt][2 * h + 1] - mnew);
                rs += s[nt][2 * h] + s[nt][2 * h + 1];
            }
            rs += __shfl_xor_sync(0xffffffffu, rs, 1);
            rs += __shfl_xor_sync(0xffffffffu, rs, 2);
            li[h] = li[h] * alpha[h] + rs;
            mi[h] = mnew;
        }
#pragma unroll
        for (int nt = 0; nt < 8; nt++)
#pragma unroll
            for (int c = 0; c < 4; c++)
                o[nt][c] *= alpha[c >> 1];

        // ---- store P (plain tf32, warp-private rows) ----
#pragma unroll
        for (int h = 0; h < 2; h++) {
            const int row = m0 + grp + 8 * h;
#pragma unroll
            for (int nt = 0; nt < 8; nt++) {
                uint2 p;
                p.x = f2tf32(s[nt][2 * h]);
                p.y = f2tf32(s[nt][2 * h + 1]);
                *(uint2*)&Ps[row * ALD + nt * 8 + 2 * tig] = p;
            }
        }
        __syncwarp();

        // ---- O += P * V  (V cvt'd at load) ----
#pragma unroll
        for (int ks = 0; ks < 8; ks++) {
            uint32_t ah[4];
            ah[0] = __float_as_uint(Ps[(m0 + grp)     * ALD + ks * 8 + tig]);
            ah[1] = __float_as_uint(Ps[(m0 + grp + 8) * ALD + ks * 8 + tig]);
            ah[2] = __float_as_uint(Ps[(m0 + grp)     * ALD + ks * 8 + tig + 4]);
            ah[3] = __float_as_uint(Ps[(m0 + grp + 8) * ALD + ks * 8 + tig + 4]);
#pragma unroll
            for (int nt = 0; nt < 8; nt++) {
                const int d = nt * 8 + grp;
                uint32_t bv2[2];
                bv2[0] = f2tf32(Vs[(ks * 8 + tig)     * ALD + d]);
                bv2[1] = f2tf32(Vs[(ks * 8 + tig + 4) * ALD + d]);
                mma_tf32(o[nt], ah, bv2);
            }
        }
        __syncthreads();   // all warps done with buf[cur] before it's refilled
    }

    // ---- epilogue ----
    float* Ob = Og + ((size_t)bh * SEQ + q0) * HD;
#pragma unroll
    for (int h = 0; h < 2; h++) {
        const int row = m0 + grp + 8 * h;
        const float inv = 1.0f / li[h];
#pragma unroll
        for (int nt = 0; nt < 8; nt++) {
            const int d = nt * 8 + 2 * tig;
            float2 r;
            r.x = o[nt][2 * h]     * inv;
            r.y = o[nt][2 * h + 1] * inv;
            *(float2*)&Ob[(size_t)row * HD + d] = r;
        }
    }
}

// ---------------------------------------------------------------------------
extern "C" void kernel_launch(void* const* d_in, const int* in_sizes, int n_in,
                              void* d_out, int out_size)
{
    const float* q  = (const float*)d_in[0];
    const float* k  = (const float*)d_in[1];
    const float* v  = (const float*)d_in[2];
    const float* Wq = (const float*)d_in[3];
    const float* bq = (const float*)d_in[4];
    const float* Wk = (const float*)d_in[5];
    const float* bk = (const float*)d_in[6];
    const float* Wv = (const float*)d_in[7];
    const float* bv = (const float*)d_in[8];
    const float* Wo = (const float*)d_in[9];
    const float* bo = (const float*)d_in[10];
    float* out = (float*)d_out;

    float *Qb, *Kb, *Vb, *Ob;
    cudaGetSymbolAddress((void**)&Qb, g_Q);
    cudaGetSymbolAddress((void**)&Kb, g_K);
    cudaGetSymbolAddress((void**)&Vb, g_V);
    cudaGetSymbolAddress((void**)&Ob, g_AO);

    cudaFuncSetAttribute(attn_tc_kernel,
                         cudaFuncAttributeMaxDynamicSharedMemorySize, ATTN_SMEM_BYTES);

    dim3 blk(256);
    dim3 gProj(DM / 128, TOK / 128);   // (8, 64)

    tgemm_kernel<0, 1><<<gProj, blk>>>(q, Wq, bq, Qb, TOK, DM, DM);
    tgemm_kernel<0, 1><<<gProj, blk>>>(k, Wk, bk, Kb, TOK, DM, DM);
    tgemm_kernel<0, 1><<<gProj, blk>>>(v, Wv, bv, Vb, TOK, DM, DM);

    attn_tc_kernel<<<dim3(SEQ / 64, BHN), dim3(128), ATTN_SMEM_BYTES>>>(Qb, Kb, Vb, Ob);

    tgemm_kernel<1, 0><<<gProj, blk>>>(Ob, Wo, bo, out, TOK, DM, DM);
}